// round 9
// baseline (speedup 1.0000x reference)
#include <cuda_runtime.h>
#include <cstdint>

// ---------------------------------------------------------------------------
// GroupedLinear: y[b, g*256+o] = sum_i x[b, g*256+i] * W[g,o,i] + bias[g,o]
// 16 independent GEMMs: M=8192, N=256, K=256, fp32 in/out.
//
// R8: 93.5us main, tensor 60%, issue 20% -> binder = LDSM->MMA dependency
// windows (2 warps/SMSP can't cover them; barrier convoys the phases).
// R9: fragment double-buffering: issue k-step j+1 LDSMs before k-step j's
// MMA burst; exposure drops 4 windows/chunk -> 1. Persistent CTAs kept.
// W pre-rounded to tf32 scratch; A uses HW tf32 truncation.
// ---------------------------------------------------------------------------

namespace gl {

constexpr int INF  = 4096;
constexpr int NG   = 16;
constexpr int GIN  = 256;          // K per group
constexpr int GOUT = 256;          // N per group
constexpr int MT   = 128;          // CTA M tile
constexpr int NT   = 128;          // CTA N tile
constexpr int KCH  = 32;           // K chunk: 32 floats = 128 B rows
constexpr int NCHUNK = 8;          // K chunks per tile
constexpr int TILES = 2048;        // 16 groups x 64 m-tiles x 2 n-tiles
constexpr int NCTA  = 304;         // 2 CTAs x 152 SMs (GB300)
constexpr int STAGES = 3;
constexpr int NTHREADS = 128;      // 4 warps, 2(M) x 2(N), warp tile 64x64

constexpr int A_BYTES = MT * KCH * 4;           // 16 KB per stage
constexpr int B_BYTES = NT * KCH * 4;           // 16 KB per stage
constexpr int STAGE_BYTES = A_BYTES + B_BYTES;  // 32 KB

constexpr int OFF_STAGE = 1024;
constexpr int SMEM_TOTAL = OFF_STAGE + STAGES * STAGE_BYTES;  // 99328 B -> 2 CTA/SM

__device__ __forceinline__ uint32_t swz(uint32_t x) {
    return x ^ ((x >> 3) & 0x70);
}

__device__ __forceinline__ void cp16(uint32_t dst, const void* src) {
    asm volatile("cp.async.cg.shared.global [%0], [%1], 16;"
                 :: "r"(dst), "l"(src) : "memory");
}

__device__ __forceinline__ uint32_t smem_u32(const void* p) {
    uint32_t a;
    asm("{ .reg .u64 t; cvta.to.shared.u64 t, %1; cvt.u32.u64 %0, t; }"
        : "=r"(a) : "l"(p));
    return a;
}

// fp32 -> tf32 round-to-nearest (used only in the W prologue kernel)
__device__ __forceinline__ float f2tf_f(float f) {
    uint32_t r;
    asm("cvt.rna.tf32.f32 %0, %1;" : "=r"(r) : "f"(f));
    return __uint_as_float(r);
}

// ldmatrix x4 on 32-bit data: each m8n8.b16 matrix = one 8x4 fp32 quadrant;
// thread T receives fp32 element (row = T/4, col = T%4) of each quadrant.
__device__ __forceinline__ void ldsm4(uint32_t& r0, uint32_t& r1,
                                      uint32_t& r2, uint32_t& r3,
                                      uint32_t addr) {
    asm volatile("ldmatrix.sync.aligned.m8n8.x4.shared.b16 {%0,%1,%2,%3}, [%4];"
                 : "=r"(r0), "=r"(r1), "=r"(r2), "=r"(r3) : "r"(addr));
}

__device__ __forceinline__ void mma_tf32(float* c,
                                         uint32_t a0, uint32_t a1,
                                         uint32_t a2, uint32_t a3,
                                         uint32_t b0, uint32_t b1) {
    asm volatile(
        "mma.sync.aligned.m16n8k8.row.col.f32.tf32.tf32.f32 "
        "{%0,%1,%2,%3}, {%4,%5,%6,%7}, {%8,%9}, {%0,%1,%2,%3};"
        : "+f"(c[0]), "+f"(c[1]), "+f"(c[2]), "+f"(c[3])
        : "r"(a0), "r"(a1), "r"(a2), "r"(a3), "r"(b0), "r"(b1));
}

} // namespace gl

using namespace gl;

// 4MB scratch: W rounded to tf32 once per launch (idempotent, deterministic).
__device__ float g_Wr[NG * GOUT * GIN];

__global__ __launch_bounds__(256, 4)
void GroupedLinear_roundW_kernel(const float4* __restrict__ W) {
    const int i = blockIdx.x * 256 + threadIdx.x;   // 1024 blocks -> 262144 float4
    float4 v = W[i];
    v.x = f2tf_f(v.x);
    v.y = f2tf_f(v.y);
    v.z = f2tf_f(v.z);
    v.w = f2tf_f(v.w);
    reinterpret_cast<float4*>(g_Wr)[i] = v;
}

__global__ __launch_bounds__(NTHREADS, 2)
void GroupedLinear_35364760715975_kernel(const float* __restrict__ x,
                                         const float* __restrict__ bias,
                                         float* __restrict__ y)
{
    extern __shared__ char smem[];
    const uint32_t sbase = smem_u32(smem);
    const int tid = threadIdx.x;
    const int bid = blockIdx.x;

    // ---- loader geometry (per thread, constant) ----
    const int lrr = tid >> 3;        // row 0..15, +16 per i
    const int lss = tid & 7;         // 16B slot within 128B row
    uint32_t dsto[8];
    #pragma unroll
    for (int i = 0; i < 8; i++)
        dsto[i] = swz((uint32_t)((lrr + i * 16) * 128 + lss * 16));

    // global chunk index q -> (tile, chunk) -> cp.async into buffer buf
    auto load_stage = [&](int q, int buf) {
        const int t    = q >> 3;
        const int kc   = q & 7;
        const int tile = bid + t * NCTA;
        const int g    = tile >> 7;
        const int rem  = tile & 127;
        const int mt   = rem >> 1;
        const int ntl  = rem & 1;
        const float* xs = x + (size_t)(mt * MT + lrr) * INF
                            + g * GIN + kc * KCH + lss * 4;
        const float* ws = g_Wr + (size_t)g * GOUT * GIN
                               + (size_t)(ntl * NT + lrr) * GIN + kc * KCH + lss * 4;
        const uint32_t abase = sbase + OFF_STAGE + buf * STAGE_BYTES;
        const uint32_t bbase = abase + A_BYTES;
        #pragma unroll
        for (int i = 0; i < 8; i++) {
            cp16(abase + dsto[i], xs + (size_t)(i * 16) * INF);
            cp16(bbase + dsto[i], ws + (size_t)(i * 16) * GIN);
        }
    };

    // tiles for this CTA: bid, bid+NCTA, ...
    const int ntiles = (TILES - 1 - bid) / NCTA + 1;
    const int qtot = ntiles * NCHUNK;

    // ---- prologue: fill 2 stages once ----
    load_stage(0, 0); asm volatile("cp.async.commit_group;" ::: "memory");
    load_stage(1, 1); asm volatile("cp.async.commit_group;" ::: "memory");

    // ---- per-warp geometry: 2(M) x 2(N) warps, warp tile 64x64 ----
    const int wid  = tid >> 5;
    const int lane = tid & 31;
    const int wm = wid >> 1;          // 0..1
    const int wn = wid & 1;           // 0..1
    const int grp = lane >> 2;        // 0..7
    const int tig = lane & 3;         // 0..3
    const int kk0 = wid & 3;          // stagger k-step order per warp

    // ldmatrix lane geometry
    const int q8 = lane >> 3;         // 0..3
    const int i8 = lane & 7;          // 0..7
    const uint32_t ix = (uint32_t)i8 << 4;
    const uint32_t aq16 = (uint32_t)((q8 >> 1) << 4);
    const uint32_t arow = (uint32_t)(((q8 & 1) * 8 + i8) * 128) + (uint32_t)(wm << 13);
    const uint32_t bq16 = (uint32_t)((q8 & 1) << 4);
    const uint32_t brow = (uint32_t)(((q8 >> 1) * 8 + i8) * 128) + (uint32_t)(wn << 13);

    float acc[4][8][4];               // [m16-tile][n8-tile][reg] = 128 regs
    #pragma unroll
    for (int a = 0; a < 4; a++)
        #pragma unroll
        for (int b = 0; b < 8; b++)
            #pragma unroll
            for (int c = 0; c < 4; c++) acc[a][b][c] = 0.f;

    // double-buffered fragments (ping-pong across k-steps)
    uint32_t af[2][4][4];
    uint32_t bf[2][8][2];

    // ---- flat persistent mainloop over (tile, chunk) ----
    int buf = 0, bufn = 2;            // q % 3, (q+2) % 3
    #pragma unroll 1
    for (int q = 0; q < qtot; q++) {
        asm volatile("cp.async.wait_group 1;" ::: "memory");
        __syncthreads();   // stage q visible; buffer (q+2)%3 free

        if (q + 2 < qtot) {
            load_stage(q + 2, bufn);
            asm volatile("cp.async.commit_group;" ::: "memory");
        } else {
            asm volatile("cp.async.commit_group;" ::: "memory"); // uniform count
        }

        const uint32_t stage = sbase + OFF_STAGE + buf * STAGE_BYTES;
        const uint32_t Arow = stage + arow;
        const uint32_t Brow = stage + A_BYTES + brow;

        // fragment batch loader for k-step index j (warp-staggered) -> slot s
        auto ldsm_step = [&](int j, int s) {
            const int kk = (j + kk0) & 3;
            const uint32_t cxA = ((uint32_t)(kk * 32) + aq16) ^ ix;
            const uint32_t cxB = ((uint32_t)(kk * 32) + bq16) ^ ix;
            #pragma unroll
            for (int mti = 0; mti < 4; mti++)
                ldsm4(af[s][mti][0], af[s][mti][1], af[s][mti][2], af[s][mti][3],
                      Arow + (uint32_t)(mti * 2048) + cxA);
            #pragma unroll
            for (int nt2 = 0; nt2 < 4; nt2++)
                ldsm4(bf[s][2 * nt2][0], bf[s][2 * nt2][1],
                      bf[s][2 * nt2 + 1][0], bf[s][2 * nt2 + 1][1],
                      Brow + (uint32_t)(nt2 * 2048) + cxB);
        };

        // ---- software-pipelined k-steps: prefetch j+1 before MMA burst j ----
        ldsm_step(0, 0);
        #pragma unroll
        for (int j = 0; j < 4; j++) {
            const int cur = j & 1;
            if (j < 3) ldsm_step(j + 1, cur ^ 1);
            #pragma unroll
            for (int mti = 0; mti < 4; mti++)
                #pragma unroll
                for (int nti = 0; nti < 8; nti++)
                    mma_tf32(acc[mti][nti],
                             af[cur][mti][0], af[cur][mti][1],
                             af[cur][mti][2], af[cur][mti][3],
                             bf[cur][nti][0], bf[cur][nti][1]);
        }

        // ---- tile boundary: inline epilogue (per-warp data, no extra sync) ----
        if ((q & 7) == 7) {
            const int tile = bid + (q >> 3) * NCTA;
            const int g    = tile >> 7;
            const int rem  = tile & 127;
            const int m0   = (rem >> 1) * MT;
            const int n0   = (rem & 1) * NT;
            const int gb   = g * GIN;

            const float* bp = bias + g * GOUT + n0 + wn * 64 + tig * 2;
            float2 bv[8];
            #pragma unroll
            for (int nti = 0; nti < 8; nti++)
                bv[nti] = *(const float2*)(bp + nti * 8);

            #pragma unroll
            for (int mti = 0; mti < 4; mti++) {
                const int row0 = m0 + wm * 64 + mti * 16 + grp;
                float* yr0 = y + (size_t)row0 * INF + gb + n0 + wn * 64 + tig * 2;
                float* yr1 = yr0 + (size_t)8 * INF;
                #pragma unroll
                for (int nti = 0; nti < 8; nti++) {
                    float2 v0, v1;
                    v0.x = acc[mti][nti][0] + bv[nti].x;
                    v0.y = acc[mti][nti][1] + bv[nti].y;
                    v1.x = acc[mti][nti][2] + bv[nti].x;
                    v1.y = acc[mti][nti][3] + bv[nti].y;
                    *(float2*)(yr0 + nti * 8) = v0;
                    *(float2*)(yr1 + nti * 8) = v1;
                    acc[mti][nti][0] = 0.f; acc[mti][nti][1] = 0.f;
                    acc[mti][nti][2] = 0.f; acc[mti][nti][3] = 0.f;
                }
            }
        }

        buf  = (buf  == 2) ? 0 : buf + 1;
        bufn = (bufn == 2) ? 0 : bufn + 1;
    }
}

extern "C" void kernel_launch(void* const* d_in, const int* in_sizes, int n_in,
                              void* d_out, int out_size) {
    const float* x  = (const float*)d_in[0];
    const float* Wt = (const float*)d_in[1];
    const float* b  = (const float*)d_in[2];
    float* y = (float*)d_out;

    cudaFuncSetAttribute(GroupedLinear_35364760715975_kernel,
                         cudaFuncAttributeMaxDynamicSharedMemorySize, SMEM_TOTAL);

    // 1) round W -> tf32 scratch (1M floats, 1024 x 256 x float4)
    GroupedLinear_roundW_kernel<<<1024, 256>>>((const float4*)Wt);

    // 2) persistent main GEMM: 304 CTAs (2 per SM on 152-SM GB300)
    GroupedLinear_35364760715975_kernel<<<NCTA, NTHREADS, SMEM_TOTAL>>>(x, b, y);
}

// round 10
// speedup vs baseline: 1.0618x; 1.0618x over previous
#include <cuda_runtime.h>
#include <cuda_fp16.h>
#include <cstdint>

// ---------------------------------------------------------------------------
// GroupedLinear: y[b, g*256+o] = sum_i x[b, g*256+i] * W[g,o,i] + bias[g,o]
// 16 independent GEMMs: M=8192, N=256, K=256, fp32 in/out.
//
// R6-R9 plateau at tensor=60%: smem crossbar (LDSM 64KB + STS 32KB per
// k32-chunk = 768cyc) exceeds tensor demand (486cyc) -> smem-bound.
// R10: fp16 path. x and W pre-converted (rne) to __device__ fp16 buffers;
// mma.m16n8k16.f16 carries 2x K per instruction and per smem byte.
// Same 128B-row swizzle/ldmatrix addressing (rows now hold k=64 halves).
// Persistent CTAs, 3-stage cp.async, 2 CTA/SM, fp32 accum + bias epilogue.
// ---------------------------------------------------------------------------

namespace gl {

constexpr int INF  = 4096;
constexpr int NG   = 16;
constexpr int GIN  = 256;          // K per group
constexpr int GOUT = 256;          // N per group
constexpr int MT   = 128;          // CTA M tile
constexpr int NT   = 128;          // CTA N tile
constexpr int KCH  = 64;           // K chunk: 64 halves = 128 B rows
constexpr int NCHUNK = 4;          // K chunks per tile (256/64)
constexpr int TILES = 2048;        // 16 groups x 64 m-tiles x 2 n-tiles
constexpr int NCTA  = 304;         // 2 CTAs x 152 SMs (GB300)
constexpr int NTHREADS = 128;      // 4 warps, 2(M) x 2(N), warp tile 64x64

constexpr int A_BYTES = MT * KCH * 2;           // 16 KB per stage
constexpr int B_BYTES = NT * KCH * 2;           // 16 KB per stage
constexpr int STAGE_BYTES = A_BYTES + B_BYTES;  // 32 KB

constexpr int OFF_STAGE = 1024;
constexpr int SMEM_TOTAL = OFF_STAGE + 3 * STAGE_BYTES;  // 99328 B -> 2 CTA/SM

__device__ __forceinline__ uint32_t swz(uint32_t x) {
    return x ^ ((x >> 3) & 0x70);
}

__device__ __forceinline__ void cp16(uint32_t dst, const void* src) {
    asm volatile("cp.async.cg.shared.global [%0], [%1], 16;"
                 :: "r"(dst), "l"(src) : "memory");
}

__device__ __forceinline__ uint32_t smem_u32(const void* p) {
    uint32_t a;
    asm("{ .reg .u64 t; cvta.to.shared.u64 t, %1; cvt.u32.u64 %0, t; }"
        : "=r"(a) : "l"(p));
    return a;
}

// genuine b16 ldmatrix x4 (fp16 data)
__device__ __forceinline__ void ldsm4(uint32_t& r0, uint32_t& r1,
                                      uint32_t& r2, uint32_t& r3,
                                      uint32_t addr) {
    asm volatile("ldmatrix.sync.aligned.m8n8.x4.shared.b16 {%0,%1,%2,%3}, [%4];"
                 : "=r"(r0), "=r"(r1), "=r"(r2), "=r"(r3) : "r"(addr));
}

__device__ __forceinline__ void mma_f16(float* c,
                                        uint32_t a0, uint32_t a1,
                                        uint32_t a2, uint32_t a3,
                                        uint32_t b0, uint32_t b1) {
    asm volatile(
        "mma.sync.aligned.m16n8k16.row.col.f32.f16.f16.f32 "
        "{%0,%1,%2,%3}, {%4,%5,%6,%7}, {%8,%9}, {%0,%1,%2,%3};"
        : "+f"(c[0]), "+f"(c[1]), "+f"(c[2]), "+f"(c[3])
        : "r"(a0), "r"(a1), "r"(a2), "r"(a3), "r"(b0), "r"(b1));
}

} // namespace gl

using namespace gl;

// fp16 copies of x (64MB) and W (2MB), produced once per launch (idempotent).
__device__ __half g_xh[8192 * 4096];
__device__ __half g_Wh[NG * GOUT * GIN];

// grid-stride fp32 -> fp16 (rne) converter, float4 -> 2x half2 per element
__global__ __launch_bounds__(256, 8)
void GroupedLinear_cvt_kernel(const float4* __restrict__ in,
                              uint2* __restrict__ out, int n4) {
    const int stride = gridDim.x * 256;
    for (int i = blockIdx.x * 256 + threadIdx.x; i < n4; i += stride) {
        float4 v = in[i];
        __half2 lo = __floats2half2_rn(v.x, v.y);
        __half2 hi = __floats2half2_rn(v.z, v.w);
        uint2 o;
        o.x = *reinterpret_cast<uint32_t*>(&lo);
        o.y = *reinterpret_cast<uint32_t*>(&hi);
        out[i] = o;
    }
}

__global__ __launch_bounds__(NTHREADS, 2)
void GroupedLinear_35364760715975_kernel(const float* __restrict__ bias,
                                         float* __restrict__ y)
{
    extern __shared__ char smem[];
    const uint32_t sbase = smem_u32(smem);
    const int tid = threadIdx.x;
    const int bid = blockIdx.x;

    // ---- loader geometry (per thread, constant) ----
    const int lrr = tid >> 3;        // row 0..15, +16 per i
    const int lss = tid & 7;         // 16B slot within 128B row
    uint32_t dsto[8];
    #pragma unroll
    for (int i = 0; i < 8; i++)
        dsto[i] = swz((uint32_t)((lrr + i * 16) * 128 + lss * 16));

    // global chunk index q -> (tile, k-chunk) -> cp.async into buffer buf
    auto load_stage = [&](int q, int buf) {
        const int t    = q >> 2;
        const int kc   = q & 3;
        const int tile = bid + t * NCTA;
        const int g    = tile >> 7;
        const int rem  = tile & 127;
        const int mt   = rem >> 1;
        const int ntl  = rem & 1;
        const __half* xs = g_xh + (size_t)(mt * MT + lrr) * INF
                                + g * GIN + kc * KCH + lss * 8;
        const __half* ws = g_Wh + (size_t)g * GOUT * GIN
                                + (size_t)(ntl * NT + lrr) * GIN + kc * KCH + lss * 8;
        const uint32_t abase = sbase + OFF_STAGE + buf * STAGE_BYTES;
        const uint32_t bbase = abase + A_BYTES;
        #pragma unroll
        for (int i = 0; i < 8; i++) {
            cp16(abase + dsto[i], xs + (size_t)(i * 16) * INF);
            cp16(bbase + dsto[i], ws + (size_t)(i * 16) * GIN);
        }
    };

    // tiles for this CTA: bid, bid+NCTA, ...
    const int ntiles = (TILES - 1 - bid) / NCTA + 1;
    const int qtot = ntiles * NCHUNK;

    // ---- prologue: fill 2 stages once ----
    load_stage(0, 0); asm volatile("cp.async.commit_group;" ::: "memory");
    load_stage(1, 1); asm volatile("cp.async.commit_group;" ::: "memory");

    // ---- per-warp geometry: 2(M) x 2(N) warps, warp tile 64x64 ----
    const int wid  = tid >> 5;
    const int lane = tid & 31;
    const int wm = wid >> 1;          // 0..1
    const int wn = wid & 1;           // 0..1
    const int grp = lane >> 2;        // 0..7
    const int tig = lane & 3;         // 0..3
    const int kk0 = wid & 3;          // stagger k-step order per warp

    // ldmatrix lane geometry (b16, canonical m16n8k16 fragments)
    const int q8 = lane >> 3;         // 0..3
    const int i8 = lane & 7;          // 0..7
    const uint32_t ix = (uint32_t)i8 << 4;
    // A: M0=(m0-7,k0-7) M1=(m8-15,k0-7) M2=(m0-7,k8-15) M3=(m8-15,k8-15)
    const uint32_t aq16 = (uint32_t)((q8 >> 1) << 4);
    const uint32_t arow = (uint32_t)(((q8 & 1) * 8 + i8) * 128) + (uint32_t)(wm << 13);
    // B: M0=(n0-7,k0-7) M1=(n0-7,k8-15) M2=(n8-15,k0-7) M3=(n8-15,k8-15)
    const uint32_t bq16 = (uint32_t)((q8 & 1) << 4);
    const uint32_t brow = (uint32_t)(((q8 >> 1) * 8 + i8) * 128) + (uint32_t)(wn << 13);

    float acc[4][8][4];               // [m16-tile][n8-tile][reg] = 128 regs
    #pragma unroll
    for (int a = 0; a < 4; a++)
        #pragma unroll
        for (int b = 0; b < 8; b++)
            #pragma unroll
            for (int c = 0; c < 4; c++) acc[a][b][c] = 0.f;

    // ---- flat persistent mainloop over (tile, k64-chunk) ----
    int buf = 0, bufn = 2;            // q % 3, (q+2) % 3
    #pragma unroll 1
    for (int q = 0; q < qtot; q++) {
        asm volatile("cp.async.wait_group 1;" ::: "memory");
        __syncthreads();   // stage q visible; buffer (q+2)%3 free

        if (q + 2 < qtot) {
            load_stage(q + 2, bufn);
            asm volatile("cp.async.commit_group;" ::: "memory");
        } else {
            asm volatile("cp.async.commit_group;" ::: "memory"); // uniform count
        }

        const uint32_t stage = sbase + OFF_STAGE + buf * STAGE_BYTES;
        const uint32_t Arow = stage + arow;
        const uint32_t Brow = stage + A_BYTES + brow;

        #pragma unroll
        for (int j = 0; j < 4; j++) {
            const int kk = (j + kk0) & 3;           // k16 step within k64 row
            const uint32_t cxA = ((uint32_t)(kk * 32) + aq16) ^ ix;
            const uint32_t cxB = ((uint32_t)(kk * 32) + bq16) ^ ix;

            // A fragments: 4 m16 tiles, one ldsm4 each (4 f16x2 regs)
            uint32_t af[4][4];
            #pragma unroll
            for (int mti = 0; mti < 4; mti++)
                ldsm4(af[mti][0], af[mti][1], af[mti][2], af[mti][3],
                      Arow + (uint32_t)(mti * 2048) + cxA);

            // B fragments: 8 n8 tiles, 4 ldsm4
            uint32_t bf[8][2];
            #pragma unroll
            for (int nt2 = 0; nt2 < 4; nt2++)
                ldsm4(bf[2 * nt2][0], bf[2 * nt2][1],
                      bf[2 * nt2 + 1][0], bf[2 * nt2 + 1][1],
                      Brow + (uint32_t)(nt2 * 2048) + cxB);

            // 32 MMAs, each k16
            #pragma unroll
            for (int mti = 0; mti < 4; mti++)
                #pragma unroll
                for (int nti = 0; nti < 8; nti++)
                    mma_f16(acc[mti][nti],
                            af[mti][0], af[mti][1], af[mti][2], af[mti][3],
                            bf[nti][0], bf[nti][1]);
        }

        // ---- tile boundary: inline epilogue (per-warp data, no extra sync) ----
        if ((q & 3) == 3) {
            const int tile = bid + (q >> 2) * NCTA;
            const int g    = tile >> 7;
            const int rem  = tile & 127;
            const int m0   = (rem >> 1) * MT;
            const int n0   = (rem & 1) * NT;
            const int gb   = g * GIN;

            const float* bp = bias + g * GOUT + n0 + wn * 64 + tig * 2;
            float2 bv[8];
            #pragma unroll
            for (int nti = 0; nti < 8; nti++)
                bv[nti] = *(const float2*)(bp + nti * 8);

            #pragma unroll
            for (int mti = 0; mti < 4; mti++) {
                const int row0 = m0 + wm * 64 + mti * 16 + grp;
                float* yr0 = y + (size_t)row0 * INF + gb + n0 + wn * 64 + tig * 2;
                float* yr1 = yr0 + (size_t)8 * INF;
                #pragma unroll
                for (int nti = 0; nti < 8; nti++) {
                    float2 v0, v1;
                    v0.x = acc[mti][nti][0] + bv[nti].x;
                    v0.y = acc[mti][nti][1] + bv[nti].y;
                    v1.x = acc[mti][nti][2] + bv[nti].x;
                    v1.y = acc[mti][nti][3] + bv[nti].y;
                    *(float2*)(yr0 + nti * 8) = v0;
                    *(float2*)(yr1 + nti * 8) = v1;
                    acc[mti][nti][0] = 0.f; acc[mti][nti][1] = 0.f;
                    acc[mti][nti][2] = 0.f; acc[mti][nti][3] = 0.f;
                }
            }
        }

        buf  = (buf  == 2) ? 0 : buf + 1;
        bufn = (bufn == 2) ? 0 : bufn + 1;
    }
}

extern "C" void kernel_launch(void* const* d_in, const int* in_sizes, int n_in,
                              void* d_out, int out_size) {
    const float* x  = (const float*)d_in[0];
    const float* Wt = (const float*)d_in[1];
    const float* b  = (const float*)d_in[2];
    float* y = (float*)d_out;

    cudaFuncSetAttribute(GroupedLinear_35364760715975_kernel,
                         cudaFuncAttributeMaxDynamicSharedMemorySize, SMEM_TOTAL);

    // 1) convert x (33.5M f32 -> 8.39M float4) and W (1M f32) to fp16 (rne)
    __half* xh_dev = nullptr;  __half* wh_dev = nullptr;
    cudaGetSymbolAddress((void**)&xh_dev, g_xh);
    cudaGetSymbolAddress((void**)&wh_dev, g_Wh);
    GroupedLinear_cvt_kernel<<<4096, 256>>>((const float4*)x,
                                            (uint2*)xh_dev, 8192 * 4096 / 4);
    GroupedLinear_cvt_kernel<<<256, 256>>>((const float4*)Wt,
                                           (uint2*)wh_dev, NG * GOUT * GIN / 4);

    // 2) persistent main GEMM: 304 CTAs (2 per SM on 152-SM GB300)
    GroupedLinear_35364760715975_kernel<<<NCTA, NTHREADS, SMEM_TOTAL>>>(b, y);
}

// round 11
// speedup vs baseline: 1.1938x; 1.1243x over previous
#include <cuda_runtime.h>
#include <cuda_fp16.h>
#include <cstdint>

// ---------------------------------------------------------------------------
// GroupedLinear: y[b, g*256+o] = sum_i x[b, g*256+i] * W[g,o,i] + bias[g,o]
// 16 independent GEMMs: M=8192, N=256, K=256, fp32 in/out.
//
// R10: 92.6us = x-cvt prepass 26.6 + W-cvt 1 + fp16 main 64.
// R11: fuse x conversion into the GEMM. CTA N=256 (full group) -> each x
// element consumed by exactly one CTA; A path = LDG fp32 -> cvt(rne) -> STS
// fp16, register-pipelined one chunk ahead. B stays cp.async from the 2MB
// W-fp16 prepass. Persistent CTAs (152), 3-stage, mma.m16n8k16.f16.
// ---------------------------------------------------------------------------

namespace gl {

constexpr int INF  = 4096;
constexpr int NG   = 16;
constexpr int GIN  = 256;          // K per group
constexpr int GOUT = 256;          // N per group
constexpr int MT   = 128;          // CTA M tile
constexpr int NT   = 256;          // CTA N tile (full group)
constexpr int KCH  = 64;           // K chunk: 64 halves = 128 B rows
constexpr int NCHUNK = 4;          // K chunks per tile (256/64)
constexpr int TILES = 1024;        // 16 groups x 64 m-tiles
constexpr int NCTA  = 152;         // 1 CTA per SM (GB300: 152 SMs)
constexpr int NTHREADS = 256;      // 8 warps, 2(M) x 4(N), warp tile 64x64

constexpr int A_BYTES = MT * KCH * 2;           // 16 KB per stage
constexpr int B_BYTES = NT * KCH * 2;           // 32 KB per stage
constexpr int STAGE_BYTES = A_BYTES + B_BYTES;  // 48 KB

constexpr int OFF_STAGE = 1024;
constexpr int SMEM_TOTAL = OFF_STAGE + 3 * STAGE_BYTES;  // 148480 B -> 1 CTA/SM

__device__ __forceinline__ uint32_t swz(uint32_t x) {
    return x ^ ((x >> 3) & 0x70);
}

__device__ __forceinline__ void cp16(uint32_t dst, const void* src) {
    asm volatile("cp.async.cg.shared.global [%0], [%1], 16;"
                 :: "r"(dst), "l"(src) : "memory");
}

__device__ __forceinline__ uint32_t smem_u32(const void* p) {
    uint32_t a;
    asm("{ .reg .u64 t; cvta.to.shared.u64 t, %1; cvt.u32.u64 %0, t; }"
        : "=r"(a) : "l"(p));
    return a;
}

__device__ __forceinline__ void ldsm4(uint32_t& r0, uint32_t& r1,
                                      uint32_t& r2, uint32_t& r3,
                                      uint32_t addr) {
    asm volatile("ldmatrix.sync.aligned.m8n8.x4.shared.b16 {%0,%1,%2,%3}, [%4];"
                 : "=r"(r0), "=r"(r1), "=r"(r2), "=r"(r3) : "r"(addr));
}

__device__ __forceinline__ void mma_f16(float* c,
                                        uint32_t a0, uint32_t a1,
                                        uint32_t a2, uint32_t a3,
                                        uint32_t b0, uint32_t b1) {
    asm volatile(
        "mma.sync.aligned.m16n8k16.row.col.f32.f16.f16.f32 "
        "{%0,%1,%2,%3}, {%4,%5,%6,%7}, {%8,%9}, {%0,%1,%2,%3};"
        : "+f"(c[0]), "+f"(c[1]), "+f"(c[2]), "+f"(c[3])
        : "r"(a0), "r"(a1), "r"(a2), "r"(a3), "r"(b0), "r"(b1));
}

__device__ __forceinline__ uint32_t h2u(__half2 h) {
    return *reinterpret_cast<uint32_t*>(&h);
}

} // namespace gl

using namespace gl;

// fp16 copy of W (2MB), produced once per launch (idempotent, deterministic).
__device__ __half g_Wh[NG * GOUT * GIN];

// grid-stride fp32 -> fp16 (rne) converter for W
__global__ __launch_bounds__(256, 8)
void GroupedLinear_cvtW_kernel(const float4* __restrict__ in,
                               uint2* __restrict__ out, int n4) {
    const int stride = gridDim.x * 256;
    for (int i = blockIdx.x * 256 + threadIdx.x; i < n4; i += stride) {
        float4 v = in[i];
        __half2 lo = __floats2half2_rn(v.x, v.y);
        __half2 hi = __floats2half2_rn(v.z, v.w);
        uint2 o;
        o.x = *reinterpret_cast<uint32_t*>(&lo);
        o.y = *reinterpret_cast<uint32_t*>(&hi);
        out[i] = o;
    }
}

__global__ __launch_bounds__(NTHREADS, 1)
void GroupedLinear_35364760715975_kernel(const float* __restrict__ x,
                                         const float* __restrict__ bias,
                                         float* __restrict__ y)
{
    extern __shared__ char smem[];
    const uint32_t sbase = smem_u32(smem);
    const int tid = threadIdx.x;
    const int bid = blockIdx.x;

    // ---- B loader geometry (cp.async from g_Wh) ----
    const int lrr = tid >> 3;        // row 0..31, +32 per i (8 iters -> 256 rows)
    const int lss = tid & 7;         // 16B slot within 128B row
    uint32_t dstoB[8];
    #pragma unroll
    for (int i = 0; i < 8; i++)
        dstoB[i] = swz((uint32_t)((lrr + i * 32) * 128 + lss * 16));

    auto loadB = [&](int q, int buf) {
        const int t  = q >> 2;
        const int kc = q & 3;
        const int g  = (bid + t * NCTA) >> 6;
        const __half* ws = g_Wh + (size_t)g * GOUT * GIN
                                + (size_t)lrr * GIN + kc * KCH + lss * 8;
        const uint32_t bbase = sbase + OFF_STAGE + buf * STAGE_BYTES + A_BYTES;
        #pragma unroll
        for (int i = 0; i < 8; i++)
            cp16(bbase + dstoB[i], ws + (size_t)(i * 32) * GIN);
    };

    // ---- A loader geometry (LDG fp32 -> cvt -> STS fp16) ----
    const int ar = tid >> 1;         // row 0..127
    const int ah = tid & 1;          // half of the 64-halves row
    uint32_t astso[4];
    #pragma unroll
    for (int j = 0; j < 4; j++)
        astso[j] = swz((uint32_t)(ar * 128 + ah * 64 + j * 16));

    float4 ldgbuf[8];                // one chunk in flight (32 floats/thread)

    auto ldgA = [&](int q) {
        const int t    = q >> 2;
        const int kc   = q & 3;
        const int tile = bid + t * NCTA;
        const int g    = tile >> 6;
        const int mt   = tile & 63;
        const float4* p = (const float4*)(x + (size_t)(mt * MT + ar) * INF
                                            + g * GIN + kc * KCH + ah * 32);
        #pragma unroll
        for (int i = 0; i < 8; i++) ldgbuf[i] = p[i];
    };

    auto stsA = [&](int buf) {
        const uint32_t ab = sbase + OFF_STAGE + buf * STAGE_BYTES;
        #pragma unroll
        for (int j = 0; j < 4; j++) {
            uint32_t h0 = h2u(__floats2half2_rn(ldgbuf[2*j].x,   ldgbuf[2*j].y));
            uint32_t h1 = h2u(__floats2half2_rn(ldgbuf[2*j].z,   ldgbuf[2*j].w));
            uint32_t h2 = h2u(__floats2half2_rn(ldgbuf[2*j+1].x, ldgbuf[2*j+1].y));
            uint32_t h3 = h2u(__floats2half2_rn(ldgbuf[2*j+1].z, ldgbuf[2*j+1].w));
            asm volatile("st.shared.v4.b32 [%0], {%1,%2,%3,%4};"
                         :: "r"(ab + astso[j]), "r"(h0), "r"(h1), "r"(h2), "r"(h3)
                         : "memory");
        }
    };

    // tiles for this CTA: bid, bid+NCTA, ...
    const int ntiles = (TILES - 1 - bid) / NCTA + 1;
    const int qtot = ntiles * NCHUNK;

    // ---- prologue ----
    ldgA(0);
    stsA(0);                               // one exposed LDG latency, once
    loadB(0, 0); asm volatile("cp.async.commit_group;" ::: "memory");
    ldgA(1);
    loadB(1, 1); asm volatile("cp.async.commit_group;" ::: "memory");

    // ---- per-warp geometry: 2(M) x 4(N) warps, warp tile 64x64 ----
    const int wid  = tid >> 5;
    const int lane = tid & 31;
    const int wm = wid >> 2;          // 0..1
    const int wn = wid & 3;           // 0..3
    const int grp = lane >> 2;        // 0..7
    const int tig = lane & 3;         // 0..3
    const int kk0 = wid & 3;          // stagger k-step order per warp

    // ldmatrix lane geometry (b16, canonical m16n8k16 fragments)
    const int q8 = lane >> 3;         // 0..3
    const int i8 = lane & 7;          // 0..7
    const uint32_t ix = (uint32_t)i8 << 4;
    const uint32_t aq16 = (uint32_t)((q8 >> 1) << 4);
    const uint32_t arow = (uint32_t)(((q8 & 1) * 8 + i8) * 128) + (uint32_t)(wm << 13);
    const uint32_t bq16 = (uint32_t)((q8 & 1) << 4);
    const uint32_t brow = (uint32_t)(((q8 >> 1) * 8 + i8) * 128) + (uint32_t)(wn << 13);

    float acc[4][8][4];               // [m16-tile][n8-tile][reg] = 128 regs
    #pragma unroll
    for (int a = 0; a < 4; a++)
        #pragma unroll
        for (int b = 0; b < 8; b++)
            #pragma unroll
            for (int c = 0; c < 4; c++) acc[a][b][c] = 0.f;

    // ---- flat persistent mainloop over (tile, k64-chunk) ----
    int buf = 0;                      // q % 3
    #pragma unroll 1
    for (int q = 0; q < qtot; q++) {
        asm volatile("cp.async.wait_group 1;" ::: "memory");
        __syncthreads();   // stage q (A STS + B cp.async) visible; buf (q+1)%3 A-free

        // A: convert+store chunk q+1 (regs loaded last iter), then prefetch q+2
        if (q + 1 < qtot) stsA((buf == 2) ? 0 : buf + 1);
        if (q + 2 < qtot) {
            ldgA(q + 2);
            loadB(q + 2, (buf == 0) ? 2 : buf - 1);
            asm volatile("cp.async.commit_group;" ::: "memory");
        } else {
            asm volatile("cp.async.commit_group;" ::: "memory"); // uniform count
        }

        const uint32_t stage = sbase + OFF_STAGE + buf * STAGE_BYTES;
        const uint32_t Arow = stage + arow;
        const uint32_t Brow = stage + A_BYTES + brow;

        #pragma unroll
        for (int j = 0; j < 4; j++) {
            const int kk = (j + kk0) & 3;           // k16 step within k64 row
            const uint32_t cxA = ((uint32_t)(kk * 32) + aq16) ^ ix;
            const uint32_t cxB = ((uint32_t)(kk * 32) + bq16) ^ ix;

            uint32_t af[4][4];
            #pragma unroll
            for (int mti = 0; mti < 4; mti++)
                ldsm4(af[mti][0], af[mti][1], af[mti][2], af[mti][3],
                      Arow + (uint32_t)(mti * 2048) + cxA);

            uint32_t bf[8][2];
            #pragma unroll
            for (int nt2 = 0; nt2 < 4; nt2++)
                ldsm4(bf[2 * nt2][0], bf[2 * nt2][1],
                      bf[2 * nt2 + 1][0], bf[2 * nt2 + 1][1],
                      Brow + (uint32_t)(nt2 * 2048) + cxB);

            #pragma unroll
            for (int mti = 0; mti < 4; mti++)
                #pragma unroll
                for (int nti = 0; nti < 8; nti++)
                    mma_f16(acc[mti][nti],
                            af[mti][0], af[mti][1], af[mti][2], af[mti][3],
                            bf[nti][0], bf[nti][1]);
        }

        // ---- tile boundary: inline epilogue (per-warp data, no extra sync) ----
        if ((q & 3) == 3) {
            const int tile = bid + (q >> 2) * NCTA;
            const int g    = tile >> 6;
            const int m0   = (tile & 63) * MT;
            const int gb   = g * GOUT;

            const float* bp = bias + gb + wn * 64 + tig * 2;
            float2 bv[8];
            #pragma unroll
            for (int nti = 0; nti < 8; nti++)
                bv[nti] = *(const float2*)(bp + nti * 8);

            #pragma unroll
            for (int mti = 0; mti < 4; mti++) {
                const int row0 = m0 + wm * 64 + mti * 16 + grp;
                float* yr0 = y + (size_t)row0 * INF + gb + wn * 64 + tig * 2;
                float* yr1 = yr0 + (size_t)8 * INF;
                #pragma unroll
                for (int nti = 0; nti < 8; nti++) {
                    float2 v0, v1;
                    v0.x = acc[mti][nti][0] + bv[nti].x;
                    v0.y = acc[mti][nti][1] + bv[nti].y;
                    v1.x = acc[mti][nti][2] + bv[nti].x;
                    v1.y = acc[mti][nti][3] + bv[nti].y;
                    *(float2*)(yr0 + nti * 8) = v0;
                    *(float2*)(yr1 + nti * 8) = v1;
                    acc[mti][nti][0] = 0.f; acc[mti][nti][1] = 0.f;
                    acc[mti][nti][2] = 0.f; acc[mti][nti][3] = 0.f;
                }
            }
        }

        buf = (buf == 2) ? 0 : buf + 1;
    }
}

extern "C" void kernel_launch(void* const* d_in, const int* in_sizes, int n_in,
                              void* d_out, int out_size) {
    const float* x  = (const float*)d_in[0];
    const float* Wt = (const float*)d_in[1];
    const float* b  = (const float*)d_in[2];
    float* y = (float*)d_out;

    cudaFuncSetAttribute(GroupedLinear_35364760715975_kernel,
                         cudaFuncAttributeMaxDynamicSharedMemorySize, SMEM_TOTAL);

    // 1) convert W (1M f32) to fp16 rne (~1us)
    __half* wh_dev = nullptr;
    cudaGetSymbolAddress((void**)&wh_dev, g_Wh);
    GroupedLinear_cvtW_kernel<<<256, 256>>>((const float4*)Wt,
                                            (uint2*)wh_dev, NG * GOUT * GIN / 4);

    // 2) persistent fused cvt+GEMM: 152 CTAs (1 per SM on GB300)
    GroupedLinear_35364760715975_kernel<<<NCTA, NTHREADS, SMEM_TOTAL>>>(x, b, y);
}